// round 9
// baseline (speedup 1.0000x reference)
#include <cuda_runtime.h>
#include <cuda_bf16.h>
#include <cstdint>

#define NODES  50000
#define NEDGES 600000
#define DD     128
#define BM     128
#define BN_EPS 1e-5f
#define SCAN_T 1024

// ---------------- scratch (no allocations allowed) ----------------
__device__ __align__(16) float g_agg[NODES * DD];   // 25.6 MB (fully written by gather)
__device__ __align__(16) float g_gX[NODES * DD];    // 25.6 MB
__device__ int   g_degout[NODES];
__device__ int   g_degin[NODES];
__device__ int   g_rowptr[NODES];
__device__ int   g_cursor[NODES];
__device__ int   g_esrc[NEDGES];
__device__ float g_nsrc[NODES];
__device__ float g_ndst[NODES];
__device__ float g_sum[DD];
__device__ float g_sumsq[DD];
__device__ __align__(16) float g_scale[DD];
__device__ __align__(16) float g_bias[DD];
// pre-split B matrices: [mat][k2*128+n] packed bf16x2 (lo half = k-even)
__device__ __align__(16) uint32_t g_bhi[2][8192];
__device__ __align__(16) uint32_t g_blo[2][8192];

// ---------------- bf16 split helpers (integer RNE, no cvt pipe) ----------------
__device__ __forceinline__ uint32_t bf16_hi_bits(float x) {
    uint32_t b = __float_as_uint(x);
    return (b + 0x7FFFu + ((b >> 16) & 1u)) & 0xFFFF0000u;
}
__device__ __forceinline__ void bpack(float ve, float vo, uint32_t& whi, uint32_t& wlo) {
    uint32_t he = bf16_hi_bits(ve), ho = bf16_hi_bits(vo);
    float re = ve - __uint_as_float(he);
    float ro = vo - __uint_as_float(ho);
    uint32_t le = bf16_hi_bits(re), lo = bf16_hi_bits(ro);
    whi = ho | (he >> 16);
    wlo = lo | (le >> 16);
}

__device__ __forceinline__ void mma_bf16(float* d, const uint32_t* a, const uint32_t* b) {
    asm volatile("mma.sync.aligned.m16n8k16.row.col.f32.bf16.bf16.f32 "
        "{%0,%1,%2,%3}, {%4,%5,%6,%7}, {%8,%9}, {%0,%1,%2,%3};"
        : "+f"(d[0]), "+f"(d[1]), "+f"(d[2]), "+f"(d[3])
        : "r"(a[0]), "r"(a[1]), "r"(a[2]), "r"(a[3]), "r"(b[0]), "r"(b[1]));
}

// smem word offsets
#define BPADW 136
#define APADW 20
#define KSTR  132
#define W_BHI 0
#define W_BLO 8704
#define W_A0  17408
#define ABUF_W 5120
#define W_KEEP 27648
#define SMEM_WORDS 44544
#define SMEM_BYTES (SMEM_WORDS * 4)   // 178176

// ---------------- kernel 0: zero small scratch ----------------
__global__ void k_init() {
    int i = blockIdx.x * blockDim.x + threadIdx.x;
    if (i < NODES / 4) {
        ((int4*)g_degout)[i] = make_int4(0, 0, 0, 0);
        ((int4*)g_degin)[i]  = make_int4(0, 0, 0, 0);
    }
    if (i < DD) { g_sum[i] = 0.f; g_sumsq[i] = 0.f; }
}

// ---------------- kernel 1: degrees ----------------
__global__ void k_deg(const int* __restrict__ src, const int* __restrict__ dst) {
    int e = blockIdx.x * blockDim.x + threadIdx.x;
    if (e < NEDGES) {
        atomicAdd(&g_degout[src[e]], 1);
        atomicAdd(&g_degin[dst[e]], 1);
    }
}

// ---------------- kernel 1b: pre-split B matrices (mat0=Wres, mat1=W) ----------------
__global__ void k_prepB(const float* __restrict__ W, const float* __restrict__ Wres) {
    int idx = blockIdx.x * blockDim.x + threadIdx.x;   // 0..16383
    int mat = idx >> 13;
    int r = idx & 8191;
    int k2 = r >> 7, n = r & 127;
    const float* B = mat ? W : Wres;
    float ve = __ldg(B + (size_t)(2 * k2) * DD + n);
    float vo = __ldg(B + (size_t)(2 * k2 + 1) * DD + n);
    uint32_t h, l;
    bpack(ve, vo, h, l);
    g_bhi[mat][r] = h;
    g_blo[mat][r] = l;
}

// ---------------- kernel 1c: exclusive scan of deg_in -> rowptr, cursor ----------------
__global__ void k_scan() {
    __shared__ int s[SCAN_T];
    int t = threadIdx.x;
    const int per = (NODES + SCAN_T - 1) / SCAN_T;   // 49
    int beg = t * per;
    int end = min(beg + per, NODES);
    int sum = 0;
    for (int i = beg; i < end; i++) sum += g_degin[i];
    s[t] = sum;
    __syncthreads();
    // Hillis-Steele inclusive scan
    for (int off = 1; off < SCAN_T; off <<= 1) {
        int v = (t >= off) ? s[t - off] : 0;
        __syncthreads();
        s[t] += v;
        __syncthreads();
    }
    int run = (t == 0) ? 0 : s[t - 1];
    for (int i = beg; i < end; i++) {
        g_rowptr[i] = run;
        g_cursor[i] = run;
        run += g_degin[i];
    }
}

// ---------------- kernel 1d: norm tables ----------------
__global__ void k_norms() {
    int i = blockIdx.x * blockDim.x + threadIdx.x;
    if (i < NODES) {
        g_nsrc[i] = rsqrtf((float)max(g_degout[i], 1));
        g_ndst[i] = rsqrtf((float)max(g_degin[i], 1));
    }
}

// ---------------- kernel 2a: fill CSR edge lists ----------------
__global__ void k_fill(const int* __restrict__ src, const int* __restrict__ dst) {
    int e = blockIdx.x * blockDim.x + threadIdx.x;
    if (e < NEDGES) {
        int d = __ldg(dst + e);
        int p = atomicAdd(&g_cursor[d], 1);
        g_esrc[p] = __ldg(src + e);
    }
}

// ---------------- kernel 2b: gather (warp per node) ----------------
// g_agg[d] = rsqrt(deg_in[d]) * sum_{e: dst=d} X[src_e] * rsqrt(deg_out[src_e])
__global__ void k_gather(const float* __restrict__ X) {
    int w    = (blockIdx.x * blockDim.x + threadIdx.x) >> 5;
    int lane = threadIdx.x & 31;
    if (w >= NODES) return;
    int beg = g_rowptr[w];
    int cnt = g_degin[w];
    float4 a = make_float4(0.f, 0.f, 0.f, 0.f);
    int i = 0;
    for (; i + 1 < cnt; i += 2) {
        int s0 = __ldg(g_esrc + beg + i);
        int s1 = __ldg(g_esrc + beg + i + 1);
        float c0 = __ldg(g_nsrc + s0);
        float c1 = __ldg(g_nsrc + s1);
        float4 v0 = __ldg((const float4*)(X + (size_t)s0 * DD) + lane);
        float4 v1 = __ldg((const float4*)(X + (size_t)s1 * DD) + lane);
        a.x += v0.x * c0; a.y += v0.y * c0; a.z += v0.z * c0; a.w += v0.w * c0;
        a.x += v1.x * c1; a.y += v1.y * c1; a.z += v1.z * c1; a.w += v1.w * c1;
    }
    if (i < cnt) {
        int s0 = __ldg(g_esrc + beg + i);
        float c0 = __ldg(g_nsrc + s0);
        float4 v0 = __ldg((const float4*)(X + (size_t)s0 * DD) + lane);
        a.x += v0.x * c0; a.y += v0.y * c0; a.z += v0.z * c0; a.w += v0.w * c0;
    }
    float nd = g_ndst[w];
    a.x *= nd; a.y *= nd; a.z *= nd; a.w *= nd;
    *((float4*)(g_agg + (size_t)w * DD) + lane) = a;
}

// ---------------- GEMM staging (512 threads) ----------------
__device__ __forceinline__ void stageB(int mat, uint32_t* __restrict__ bhi,
                                       uint32_t* __restrict__ blo, int tid) {
    #pragma unroll
    for (int it = 0; it < 4; it++) {
        int idx = tid + it * 512;
        int k2 = idx >> 5, n4 = idx & 31;
        uint4 h = __ldg((const uint4*)(g_bhi[mat] + k2 * 128 + n4 * 4));
        uint4 l = __ldg((const uint4*)(g_blo[mat] + k2 * 128 + n4 * 4));
        *(uint4*)(bhi + k2 * BPADW + n4 * 4) = h;
        *(uint4*)(blo + k2 * BPADW + n4 * 4) = l;
    }
}

__device__ __forceinline__ void ldA(const float* __restrict__ srcA, int m0, int tid,
                                    int kc, float4* a_pf) {
    int m = tid >> 2, kw4 = tid & 3;
    int gm = m0 + m;
    int k = kc * 32 + kw4 * 8;
    if (gm < NODES) {
        a_pf[0] = __ldg((const float4*)(srcA + (size_t)gm * DD + k));
        a_pf[1] = __ldg((const float4*)(srcA + (size_t)gm * DD + k + 4));
    } else {
        a_pf[0] = make_float4(0.f, 0.f, 0.f, 0.f);
        a_pf[1] = make_float4(0.f, 0.f, 0.f, 0.f);
    }
}

__device__ __forceinline__ void stA(uint32_t* __restrict__ ahi, uint32_t* __restrict__ alo,
                                    int tid, const float4* a_pf) {
    int m = tid >> 2, kw4 = tid & 3;
    float4 f0 = a_pf[0], f1 = a_pf[1];
    uint32_t h0, l0, h1, l1, h2, l2, h3, l3;
    bpack(f0.x, f0.y, h0, l0);
    bpack(f0.z, f0.w, h1, l1);
    bpack(f1.x, f1.y, h2, l2);
    bpack(f1.z, f1.w, h3, l3);
    uint32_t* ph = ahi + m * APADW + kw4 * 4;
    uint32_t* pl = alo + m * APADW + kw4 * 4;
    ph[0] = h0; ph[1] = h1; ph[2] = h2; ph[3] = h3;
    pl[0] = l0; pl[1] = l1; pl[2] = l2; pl[3] = l3;
}

// ---------------- one GEMM phase: acc += srcA[m0:m0+128, :] @ B[mat] (3xBF16) ----------------
__device__ __forceinline__ void run_phase(const float* __restrict__ srcA, int mat,
                                          uint32_t* __restrict__ smw, int m0, int tid,
                                          float acc[2][4][4]) {
    uint32_t* Bhi = smw + W_BHI;
    uint32_t* Blo = smw + W_BLO;
    const int lane = tid & 31, wid = tid >> 5;
    const int wm = (wid >> 2) * 32;
    const int wn = (wid & 3) * 32;
    const int gr = lane >> 2, kq = lane & 3;

    stageB(mat, Bhi, Blo, tid);

    float4 a_pf[2];
    ldA(srcA, m0, tid, 0, a_pf);

    #pragma unroll 1
    for (int kc = 0; kc < 4; kc++) {
        uint32_t* Ahi = smw + W_A0 + (kc & 1) * ABUF_W;
        uint32_t* Alo = Ahi + 2560;
        stA(Ahi, Alo, tid, a_pf);
        __syncthreads();
        if (kc < 3) ldA(srcA, m0, tid, kc + 1, a_pf);

        #pragma unroll
        for (int ls = 0; ls < 2; ls++) {
            int ak2 = ls * 8;
            int bk2 = kc * 16 + ls * 8;
            uint32_t ah[2][4], al[2][4], bh[4][2], bl[4][2];
            #pragma unroll
            for (int mt = 0; mt < 2; mt++) {
                int r = wm + mt * 16 + gr;
                const uint32_t* p = Ahi + r * APADW + ak2 + kq;
                const uint32_t* q = Alo + r * APADW + ak2 + kq;
                ah[mt][0] = p[0];
                ah[mt][1] = p[8 * APADW];
                ah[mt][2] = p[4];
                ah[mt][3] = p[8 * APADW + 4];
                al[mt][0] = q[0];
                al[mt][1] = q[8 * APADW];
                al[mt][2] = q[4];
                al[mt][3] = q[8 * APADW + 4];
            }
            #pragma unroll
            for (int nt = 0; nt < 4; nt++) {
                int c = wn + nt * 8 + gr;
                const uint32_t* p = Bhi + (bk2 + kq) * BPADW + c;
                const uint32_t* q = Blo + (bk2 + kq) * BPADW + c;
                bh[nt][0] = p[0];
                bh[nt][1] = p[4 * BPADW];
                bl[nt][0] = q[0];
                bl[nt][1] = q[4 * BPADW];
            }
            #pragma unroll
            for (int mt = 0; mt < 2; mt++)
                #pragma unroll
                for (int nt = 0; nt < 4; nt++) {
                    mma_bf16(acc[mt][nt], ah[mt], bh[nt]);
                    mma_bf16(acc[mt][nt], al[mt], bh[nt]);
                    mma_bf16(acc[mt][nt], ah[mt], bl[nt]);
                }
        }
        __syncthreads();
    }
}

// ---------------- kernel 3: bf16 mma dual GEMM + fused BN stats (512 thr) ----------------
__global__ void __launch_bounds__(512, 1)
k_gemm_mma(const float* __restrict__ X) {
    extern __shared__ uint32_t smw[];
    const int tid = threadIdx.x;
    const int m0 = blockIdx.x * BM;
    const int lane = tid & 31, wid = tid >> 5;
    const int wm = (wid >> 2) * 32, wn = (wid & 3) * 32;
    const int gr = lane >> 2, kq = lane & 3;
    float* keep = (float*)(smw + W_KEEP);

    float acc[2][4][4];

    // ---- phase 1: residual X @ Wres (mat 0) ----
    #pragma unroll
    for (int mt = 0; mt < 2; mt++)
        #pragma unroll
        for (int nt = 0; nt < 4; nt++)
            #pragma unroll
            for (int q = 0; q < 4; q++) acc[mt][nt][q] = 0.f;
    run_phase(X, 0, smw, m0, tid, acc);

    #pragma unroll
    for (int mt = 0; mt < 2; mt++) {
        int r0 = wm + mt * 16 + gr;
        int r1 = r0 + 8;
        #pragma unroll
        for (int nt = 0; nt < 4; nt++) {
            int c = wn + nt * 8 + kq * 2;
            *(float2*)(keep + r0 * KSTR + c) =
                make_float2(fmaxf(acc[mt][nt][0], 0.f), fmaxf(acc[mt][nt][1], 0.f));
            *(float2*)(keep + r1 * KSTR + c) =
                make_float2(fmaxf(acc[mt][nt][2], 0.f), fmaxf(acc[mt][nt][3], 0.f));
            #pragma unroll
            for (int q = 0; q < 4; q++) acc[mt][nt][q] = 0.f;
        }
    }

    // ---- phase 2: conv agg @ W (mat 1); norm_dst already folded into g_agg ----
    run_phase(g_agg, 1, smw, m0, tid, acc);

    // ---- epilogue ----
    float cs[8], cq[8];
    #pragma unroll
    for (int j = 0; j < 8; j++) { cs[j] = 0.f; cq[j] = 0.f; }

    #pragma unroll
    for (int mt = 0; mt < 2; mt++) {
        int lr0 = wm + mt * 16 + gr;
        int lr1 = lr0 + 8;
        int r0 = m0 + lr0, r1 = m0 + lr1;
        #pragma unroll
        for (int nt = 0; nt < 4; nt++) {
            int c = wn + nt * 8 + kq * 2;
            float2 k0 = *(float2*)(keep + lr0 * KSTR + c);
            float2 k1 = *(float2*)(keep + lr1 * KSTR + c);
            float v0 = k0.x + fmaxf(acc[mt][nt][0], 0.f);
            float v1 = k0.y + fmaxf(acc[mt][nt][1], 0.f);
            float v2 = k1.x + fmaxf(acc[mt][nt][2], 0.f);
            float v3 = k1.y + fmaxf(acc[mt][nt][3], 0.f);
            if (r0 < NODES) *(float2*)(g_gX + (size_t)r0 * DD + c) = make_float2(v0, v1);
            if (r1 < NODES) *(float2*)(g_gX + (size_t)r1 * DD + c) = make_float2(v2, v3);
            if (r0 >= NODES) { v0 = 0.f; v1 = 0.f; }
            if (r1 >= NODES) { v2 = 0.f; v3 = 0.f; }
            cs[2 * nt + 0] += v0 + v2;
            cs[2 * nt + 1] += v1 + v3;
            cq[2 * nt + 0] += v0 * v0 + v2 * v2;
            cq[2 * nt + 1] += v1 * v1 + v3 * v3;
        }
    }

    #pragma unroll
    for (int j = 0; j < 8; j++) {
        #pragma unroll
        for (int off = 16; off >= 4; off >>= 1) {
            cs[j] += __shfl_xor_sync(0xFFFFFFFF, cs[j], off);
            cq[j] += __shfl_xor_sync(0xFFFFFFFF, cq[j], off);
        }
    }

    __syncthreads();
    float* redsum = (float*)(smw + W_A0);
    float* redsq  = redsum + 128;
    if (tid < 128) { redsum[tid] = 0.f; redsq[tid] = 0.f; }
    __syncthreads();
    if (gr == 0) {
        #pragma unroll
        for (int j = 0; j < 8; j++) {
            int c = wn + (j >> 1) * 8 + kq * 2 + (j & 1);
            atomicAdd(&redsum[c], cs[j]);
            atomicAdd(&redsq[c], cq[j]);
        }
    }
    __syncthreads();
    if (tid < 128) {
        atomicAdd(&g_sum[tid], redsum[tid]);
        atomicAdd(&g_sumsq[tid], redsq[tid]);
    }
}

// ---------------- kernel 4: finalize BN affine coefficients ----------------
__global__ void k_finalize(const float* __restrict__ gamma, const float* __restrict__ beta) {
    int c = threadIdx.x;
    const float invN = 1.f / (float)NODES;
    float mean = g_sum[c] * invN;
    float var  = fmaxf(g_sumsq[c] * invN - mean * mean, 0.f);
    float inv  = rsqrtf(var + BN_EPS);
    float s = gamma[c] * inv;
    g_scale[c] = s;
    g_bias[c]  = beta[c] - s * mean;
}

// ---------------- kernel 5: apply BN ----------------
__global__ void k_bn(float* __restrict__ out) {
    int i = blockIdx.x * blockDim.x + threadIdx.x;
    if (i >= NODES * DD / 4) return;
    int c4 = i & 31;
    float4 sc = ((const float4*)g_scale)[c4];
    float4 bi = ((const float4*)g_bias)[c4];
    float4 v  = ((const float4*)g_gX)[i];
    float4 o;
    o.x = fmaf(v.x, sc.x, bi.x);
    o.y = fmaf(v.y, sc.y, bi.y);
    o.z = fmaf(v.z, sc.z, bi.z);
    o.w = fmaf(v.w, sc.w, bi.w);
    ((float4*)out)[i] = o;
}

// ---------------- launch ----------------
extern "C" void kernel_launch(void* const* d_in, const int* in_sizes, int n_in,
                              void* d_out, int out_size) {
    const float* X     = (const float*)d_in[0];
    const float* W     = (const float*)d_in[1];
    const float* Wres  = (const float*)d_in[2];
    const float* gamma = (const float*)d_in[3];
    const float* beta  = (const float*)d_in[4];
    const int*   src   = (const int*)d_in[5];
    const int*   dst   = (const int*)d_in[6];
    float* out = (float*)d_out;

    (void)in_sizes; (void)n_in; (void)out_size;

    cudaFuncSetAttribute(k_gemm_mma, cudaFuncAttributeMaxDynamicSharedMemorySize, SMEM_BYTES);

    k_init<<<(NODES / 4 + 255) / 256, 256>>>();
    k_deg<<<(NEDGES + 255) / 256, 256>>>(src, dst);
    k_prepB<<<64, 256>>>(W, Wres);
    k_scan<<<1, SCAN_T>>>();
    k_norms<<<(NODES + 255) / 256, 256>>>();
    k_fill<<<(NEDGES + 255) / 256, 256>>>(src, dst);
    k_gather<<<(NODES * 32 + 255) / 256, 256>>>(X);
    k_gemm_mma<<<(NODES + BM - 1) / BM, 512, SMEM_BYTES>>>(X);
    k_finalize<<<1, DD>>>(gamma, beta);
    k_bn<<<(NODES * DD / 4 + 255) / 256, 256>>>(out);
}

// round 10
// speedup vs baseline: 1.6054x; 1.6054x over previous
#include <cuda_runtime.h>
#include <cuda_bf16.h>
#include <cstdint>

#define NODES  50000
#define NEDGES 600000
#define DD     128
#define BM     128
#define BN_EPS 1e-5f
#define NBLK   ((NODES + 255) / 256)   // 196

// ---------------- scratch (no allocations allowed) ----------------
__device__ __align__(16) float g_agg[NODES * DD];   // 25.6 MB (fully written by gather)
__device__ __align__(16) float g_gX[NODES * DD];    // 25.6 MB
__device__ int   g_degout[NODES];
__device__ int   g_degin[NODES];
__device__ int   g_rowptr[NODES];
__device__ int   g_cursor[NODES];
__device__ int   g_esrc[NEDGES];
__device__ int   g_blksum[NBLK];
__device__ int   g_blkoff[NBLK];
__device__ float g_nsrc[NODES];
__device__ float g_ndst[NODES];
__device__ float g_sum[DD];
__device__ float g_sumsq[DD];
__device__ __align__(16) float g_scale[DD];
__device__ __align__(16) float g_bias[DD];
// pre-split B matrices: [mat][k2*128+n] packed bf16x2 (lo half = k-even)
__device__ __align__(16) uint32_t g_bhi[2][8192];
__device__ __align__(16) uint32_t g_blo[2][8192];

// ---------------- bf16 split helpers (integer RNE, no cvt pipe) ----------------
__device__ __forceinline__ uint32_t bf16_hi_bits(float x) {
    uint32_t b = __float_as_uint(x);
    return (b + 0x7FFFu + ((b >> 16) & 1u)) & 0xFFFF0000u;
}
__device__ __forceinline__ void bpack(float ve, float vo, uint32_t& whi, uint32_t& wlo) {
    uint32_t he = bf16_hi_bits(ve), ho = bf16_hi_bits(vo);
    float re = ve - __uint_as_float(he);
    float ro = vo - __uint_as_float(ho);
    uint32_t le = bf16_hi_bits(re), lo = bf16_hi_bits(ro);
    whi = ho | (he >> 16);
    wlo = lo | (le >> 16);
}

__device__ __forceinline__ void mma_bf16(float* d, const uint32_t* a, const uint32_t* b) {
    asm volatile("mma.sync.aligned.m16n8k16.row.col.f32.bf16.bf16.f32 "
        "{%0,%1,%2,%3}, {%4,%5,%6,%7}, {%8,%9}, {%0,%1,%2,%3};"
        : "+f"(d[0]), "+f"(d[1]), "+f"(d[2]), "+f"(d[3])
        : "r"(a[0]), "r"(a[1]), "r"(a[2]), "r"(a[3]), "r"(b[0]), "r"(b[1]));
}

// smem word offsets
#define BPADW 136
#define APADW 20
#define KSTR  132
#define W_BHI 0
#define W_BLO 8704
#define W_A0  17408
#define ABUF_W 5120
#define W_KEEP 27648
#define SMEM_WORDS 44544
#define SMEM_BYTES (SMEM_WORDS * 4)   // 178176

// ---------------- kernel 0: zero small scratch ----------------
__global__ void k_init() {
    int i = blockIdx.x * blockDim.x + threadIdx.x;
    if (i < NODES / 4) {
        ((int4*)g_degout)[i] = make_int4(0, 0, 0, 0);
        ((int4*)g_degin)[i]  = make_int4(0, 0, 0, 0);
    }
    if (i < DD) { g_sum[i] = 0.f; g_sumsq[i] = 0.f; }
}

// ---------------- kernel 1: degrees ----------------
__global__ void k_deg(const int* __restrict__ src, const int* __restrict__ dst) {
    int e = blockIdx.x * blockDim.x + threadIdx.x;
    if (e < NEDGES) {
        atomicAdd(&g_degout[src[e]], 1);
        atomicAdd(&g_degin[dst[e]], 1);
    }
}

// ---------------- kernel 1b: pre-split B matrices (mat0=Wres, mat1=W) ----------------
__global__ void k_prepB(const float* __restrict__ W, const float* __restrict__ Wres) {
    int idx = blockIdx.x * blockDim.x + threadIdx.x;   // 0..16383
    int mat = idx >> 13;
    int r = idx & 8191;
    int k2 = r >> 7, n = r & 127;
    const float* B = mat ? W : Wres;
    float ve = __ldg(B + (size_t)(2 * k2) * DD + n);
    float vo = __ldg(B + (size_t)(2 * k2 + 1) * DD + n);
    uint32_t h, l;
    bpack(ve, vo, h, l);
    g_bhi[mat][r] = h;
    g_blo[mat][r] = l;
}

// ---------------- hierarchical exclusive scan of deg_in ----------------
// stage 1: per-block sums (196 x 256)
__global__ void k_scan1() {
    __shared__ int s[256];
    int t = threadIdx.x;
    int i = blockIdx.x * 256 + t;
    s[t] = (i < NODES) ? g_degin[i] : 0;
    __syncthreads();
    #pragma unroll
    for (int off = 128; off > 0; off >>= 1) {
        if (t < off) s[t] += s[t + off];
        __syncthreads();
    }
    if (t == 0) g_blksum[blockIdx.x] = s[0];
}

// stage 2: scan 196 block sums (1 x 256)
__global__ void k_scan2() {
    __shared__ int s[256];
    int t = threadIdx.x;
    s[t] = (t < NBLK) ? g_blksum[t] : 0;
    __syncthreads();
    #pragma unroll
    for (int off = 1; off < 256; off <<= 1) {
        int v = (t >= off) ? s[t - off] : 0;
        __syncthreads();
        s[t] += v;
        __syncthreads();
    }
    if (t < NBLK) g_blkoff[t] = (t == 0) ? 0 : s[t - 1];
}

// stage 3: local exclusive scan + base -> rowptr/cursor; also norm tables
__global__ void k_scan3() {
    __shared__ int s[256];
    int t = threadIdx.x;
    int i = blockIdx.x * 256 + t;
    int v = (i < NODES) ? g_degin[i] : 0;
    s[t] = v;
    __syncthreads();
    #pragma unroll
    for (int off = 1; off < 256; off <<= 1) {
        int u = (t >= off) ? s[t - off] : 0;
        __syncthreads();
        s[t] += u;
        __syncthreads();
    }
    if (i < NODES) {
        int excl = s[t] - v + g_blkoff[blockIdx.x];
        g_rowptr[i] = excl;
        g_cursor[i] = excl;
        g_nsrc[i] = rsqrtf((float)max(g_degout[i], 1));
        g_ndst[i] = rsqrtf((float)max(v, 1));
    }
}

// ---------------- kernel 2a: fill CSR edge lists ----------------
__global__ void k_fill(const int* __restrict__ src, const int* __restrict__ dst) {
    int e = blockIdx.x * blockDim.x + threadIdx.x;
    if (e < NEDGES) {
        int d = __ldg(dst + e);
        int p = atomicAdd(&g_cursor[d], 1);
        g_esrc[p] = __ldg(src + e);
    }
}

// ---------------- kernel 2b: gather (warp per node) ----------------
// g_agg[d] = rsqrt(deg_in[d]) * sum_{e: dst=d} X[src_e] * rsqrt(deg_out[src_e])
__global__ void k_gather(const float* __restrict__ X) {
    int w    = (blockIdx.x * blockDim.x + threadIdx.x) >> 5;
    int lane = threadIdx.x & 31;
    if (w >= NODES) return;
    int beg = g_rowptr[w];
    int cnt = g_degin[w];
    float4 a = make_float4(0.f, 0.f, 0.f, 0.f);
    int i = 0;
    for (; i + 1 < cnt; i += 2) {
        int s0 = __ldg(g_esrc + beg + i);
        int s1 = __ldg(g_esrc + beg + i + 1);
        float c0 = __ldg(g_nsrc + s0);
        float c1 = __ldg(g_nsrc + s1);
        float4 v0 = __ldg((const float4*)(X + (size_t)s0 * DD) + lane);
        float4 v1 = __ldg((const float4*)(X + (size_t)s1 * DD) + lane);
        a.x += v0.x * c0; a.y += v0.y * c0; a.z += v0.z * c0; a.w += v0.w * c0;
        a.x += v1.x * c1; a.y += v1.y * c1; a.z += v1.z * c1; a.w += v1.w * c1;
    }
    if (i < cnt) {
        int s0 = __ldg(g_esrc + beg + i);
        float c0 = __ldg(g_nsrc + s0);
        float4 v0 = __ldg((const float4*)(X + (size_t)s0 * DD) + lane);
        a.x += v0.x * c0; a.y += v0.y * c0; a.z += v0.z * c0; a.w += v0.w * c0;
    }
    float nd = g_ndst[w];
    a.x *= nd; a.y *= nd; a.z *= nd; a.w *= nd;
    *((float4*)(g_agg + (size_t)w * DD) + lane) = a;
}

// ---------------- GEMM staging (512 threads) ----------------
__device__ __forceinline__ void stageB(int mat, uint32_t* __restrict__ bhi,
                                       uint32_t* __restrict__ blo, int tid) {
    #pragma unroll
    for (int it = 0; it < 4; it++) {
        int idx = tid + it * 512;
        int k2 = idx >> 5, n4 = idx & 31;
        uint4 h = __ldg((const uint4*)(g_bhi[mat] + k2 * 128 + n4 * 4));
        uint4 l = __ldg((const uint4*)(g_blo[mat] + k2 * 128 + n4 * 4));
        *(uint4*)(bhi + k2 * BPADW + n4 * 4) = h;
        *(uint4*)(blo + k2 * BPADW + n4 * 4) = l;
    }
}

__device__ __forceinline__ void ldA(const float* __restrict__ srcA, int m0, int tid,
                                    int kc, float4* a_pf) {
    int m = tid >> 2, kw4 = tid & 3;
    int gm = m0 + m;
    int k = kc * 32 + kw4 * 8;
    if (gm < NODES) {
        a_pf[0] = __ldg((const float4*)(srcA + (size_t)gm * DD + k));
        a_pf[1] = __ldg((const float4*)(srcA + (size_t)gm * DD + k + 4));
    } else {
        a_pf[0] = make_float4(0.f, 0.f, 0.f, 0.f);
        a_pf[1] = make_float4(0.f, 0.f, 0.f, 0.f);
    }
}

__device__ __forceinline__ void stA(uint32_t* __restrict__ ahi, uint32_t* __restrict__ alo,
                                    int tid, const float4* a_pf) {
    int m = tid >> 2, kw4 = tid & 3;
    float4 f0 = a_pf[0], f1 = a_pf[1];
    uint32_t h0, l0, h1, l1, h2, l2, h3, l3;
    bpack(f0.x, f0.y, h0, l0);
    bpack(f0.z, f0.w, h1, l1);
    bpack(f1.x, f1.y, h2, l2);
    bpack(f1.z, f1.w, h3, l3);
    uint32_t* ph = ahi + m * APADW + kw4 * 4;
    uint32_t* pl = alo + m * APADW + kw4 * 4;
    ph[0] = h0; ph[1] = h1; ph[2] = h2; ph[3] = h3;
    pl[0] = l0; pl[1] = l1; pl[2] = l2; pl[3] = l3;
}

// ---------------- one GEMM phase: acc += srcA[m0:m0+128, :] @ B[mat] (3xBF16) ----------------
__device__ __forceinline__ void run_phase(const float* __restrict__ srcA, int mat,
                                          uint32_t* __restrict__ smw, int m0, int tid,
                                          float acc[2][4][4]) {
    uint32_t* Bhi = smw + W_BHI;
    uint32_t* Blo = smw + W_BLO;
    const int lane = tid & 31, wid = tid >> 5;
    const int wm = (wid >> 2) * 32;
    const int wn = (wid & 3) * 32;
    const int gr = lane >> 2, kq = lane & 3;

    stageB(mat, Bhi, Blo, tid);

    float4 a_pf[2];
    ldA(srcA, m0, tid, 0, a_pf);

    #pragma unroll 1
    for (int kc = 0; kc < 4; kc++) {
        uint32_t* Ahi = smw + W_A0 + (kc & 1) * ABUF_W;
        uint32_t* Alo = Ahi + 2560;
        stA(Ahi, Alo, tid, a_pf);
        __syncthreads();
        if (kc < 3) ldA(srcA, m0, tid, kc + 1, a_pf);

        #pragma unroll
        for (int ls = 0; ls < 2; ls++) {
            int ak2 = ls * 8;
            int bk2 = kc * 16 + ls * 8;
            uint32_t ah[2][4], al[2][4], bh[4][2], bl[4][2];
            #pragma unroll
            for (int mt = 0; mt < 2; mt++) {
                int r = wm + mt * 16 + gr;
                const uint32_t* p = Ahi + r * APADW + ak2 + kq;
                const uint32_t* q = Alo + r * APADW + ak2 + kq;
                ah[mt][0] = p[0];
                ah[mt][1] = p[8 * APADW];
                ah[mt][2] = p[4];
                ah[mt][3] = p[8 * APADW + 4];
                al[mt][0] = q[0];
                al[mt][1] = q[8 * APADW];
                al[mt][2] = q[4];
                al[mt][3] = q[8 * APADW + 4];
            }
            #pragma unroll
            for (int nt = 0; nt < 4; nt++) {
                int c = wn + nt * 8 + gr;
                const uint32_t* p = Bhi + (bk2 + kq) * BPADW + c;
                const uint32_t* q = Blo + (bk2 + kq) * BPADW + c;
                bh[nt][0] = p[0];
                bh[nt][1] = p[4 * BPADW];
                bl[nt][0] = q[0];
                bl[nt][1] = q[4 * BPADW];
            }
            #pragma unroll
            for (int mt = 0; mt < 2; mt++)
                #pragma unroll
                for (int nt = 0; nt < 4; nt++) {
                    mma_bf16(acc[mt][nt], ah[mt], bh[nt]);
                    mma_bf16(acc[mt][nt], al[mt], bh[nt]);
                    mma_bf16(acc[mt][nt], ah[mt], bl[nt]);
                }
        }
        __syncthreads();
    }
}

// ---------------- kernel 3: bf16 mma dual GEMM + fused BN stats (512 thr) ----------------
__global__ void __launch_bounds__(512, 1)
k_gemm_mma(const float* __restrict__ X) {
    extern __shared__ uint32_t smw[];
    const int tid = threadIdx.x;
    const int m0 = blockIdx.x * BM;
    const int lane = tid & 31, wid = tid >> 5;
    const int wm = (wid >> 2) * 32, wn = (wid & 3) * 32;
    const int gr = lane >> 2, kq = lane & 3;
    float* keep = (float*)(smw + W_KEEP);

    float acc[2][4][4];

    // ---- phase 1: residual X @ Wres (mat 0) ----
    #pragma unroll
    for (int mt = 0; mt < 2; mt++)
        #pragma unroll
        for (int nt = 0; nt < 4; nt++)
            #pragma unroll
            for (int q = 0; q < 4; q++) acc[mt][nt][q] = 0.f;
    run_phase(X, 0, smw, m0, tid, acc);

    #pragma unroll
    for (int mt = 0; mt < 2; mt++) {
        int r0 = wm + mt * 16 + gr;
        int r1 = r0 + 8;
        #pragma unroll
        for (int nt = 0; nt < 4; nt++) {
            int c = wn + nt * 8 + kq * 2;
            *(float2*)(keep + r0 * KSTR + c) =
                make_float2(fmaxf(acc[mt][nt][0], 0.f), fmaxf(acc[mt][nt][1], 0.f));
            *(float2*)(keep + r1 * KSTR + c) =
                make_float2(fmaxf(acc[mt][nt][2], 0.f), fmaxf(acc[mt][nt][3], 0.f));
            #pragma unroll
            for (int q = 0; q < 4; q++) acc[mt][nt][q] = 0.f;
        }
    }

    // ---- phase 2: conv agg @ W (mat 1); norm_dst already folded into g_agg ----
    run_phase(g_agg, 1, smw, m0, tid, acc);

    // ---- epilogue ----
    float cs[8], cq[8];
    #pragma unroll
    for (int j = 0; j < 8; j++) { cs[j] = 0.f; cq[j] = 0.f; }

    #pragma unroll
    for (int mt = 0; mt < 2; mt++) {
        int lr0 = wm + mt * 16 + gr;
        int lr1 = lr0 + 8;
        int r0 = m0 + lr0, r1 = m0 + lr1;
        #pragma unroll
        for (int nt = 0; nt < 4; nt++) {
            int c = wn + nt * 8 + kq * 2;
            float2 k0 = *(float2*)(keep + lr0 * KSTR + c);
            float2 k1 = *(float2*)(keep + lr1 * KSTR + c);
            float v0 = k0.x + fmaxf(acc[mt][nt][0], 0.f);
            float v1 = k0.y + fmaxf(acc[mt][nt][1], 0.f);
            float v2 = k1.x + fmaxf(acc[mt][nt][2], 0.f);
            float v3 = k1.y + fmaxf(acc[mt][nt][3], 0.f);
            if (r0 < NODES) *(float2*)(g_gX + (size_t)r0 * DD + c) = make_float2(v0, v1);
            if (r1 < NODES) *(float2*)(g_gX + (size_t)r1 * DD + c) = make_float2(v2, v3);
            if (r0 >= NODES) { v0 = 0.f; v1 = 0.f; }
            if (r1 >= NODES) { v2 = 0.f; v3 = 0.f; }
            cs[2 * nt + 0] += v0 + v2;
            cs[2 * nt + 1] += v1 + v3;
            cq[2 * nt + 0] += v0 * v0 + v2 * v2;
            cq[2 * nt + 1] += v1 * v1 + v3 * v3;
        }
    }

    #pragma unroll
    for (int j = 0; j < 8; j++) {
        #pragma unroll
        for (int off = 16; off >= 4; off >>= 1) {
            cs[j] += __shfl_xor_sync(0xFFFFFFFF, cs[j], off);
            cq[j] += __shfl_xor_sync(0xFFFFFFFF, cq[j], off);
        }
    }

    __syncthreads();
    float* redsum = (float*)(smw + W_A0);
    float* redsq  = redsum + 128;
    if (tid < 128) { redsum[tid] = 0.f; redsq[tid] = 0.f; }
    __syncthreads();
    if (gr == 0) {
        #pragma unroll
        for (int j = 0; j < 8; j++) {
            int c = wn + (j >> 1) * 8 + kq * 2 + (j & 1);
            atomicAdd(&redsum[c], cs[j]);
            atomicAdd(&redsq[c], cq[j]);
        }
    }
    __syncthreads();
    if (tid < 128) {
        atomicAdd(&g_sum[tid], redsum[tid]);
        atomicAdd(&g_sumsq[tid], redsq[tid]);
    }
}

// ---------------- kernel 4: finalize BN affine coefficients ----------------
__global__ void k_finalize(const float* __restrict__ gamma, const float* __restrict__ beta) {
    int c = threadIdx.x;
    const float invN = 1.f / (float)NODES;
    float mean = g_sum[c] * invN;
    float var  = fmaxf(g_sumsq[c] * invN - mean * mean, 0.f);
    float inv  = rsqrtf(var + BN_EPS);
    float s = gamma[c] * inv;
    g_scale[c] = s;
    g_bias[c]  = beta[c] - s * mean;
}

// ---------------- kernel 5: apply BN ----------------
__global__ void k_bn(float* __restrict__ out) {
    int i = blockIdx.x * blockDim.x + threadIdx.x;
    if (i >= NODES * DD / 4) return;
    int c4 = i & 31;
    float4 sc = ((const float4*)g_scale)[c4];
    float4 bi = ((const float4*)g_bias)[c4];
    float4 v  = ((const float4*)g_gX)[i];
    float4 o;
    o.x = fmaf(v.x, sc.x, bi.x);
    o.y = fmaf(v.y, sc.y, bi.y);
    o.z = fmaf(v.z, sc.z, bi.z);
    o.w = fmaf(v.w, sc.w, bi.w);
    ((float4*)out)[i] = o;
}

// ---------------- launch ----------------
extern "C" void kernel_launch(void* const* d_in, const int* in_sizes, int n_in,
                              void* d_out, int out_size) {
    const float* X     = (const float*)d_in[0];
    const float* W     = (const float*)d_in[1];
    const float* Wres  = (const float*)d_in[2];
    const float* gamma = (const float*)d_in[3];
    const float* beta  = (const float*)d_in[4];
    const int*   src   = (const int*)d_in[5];
    const int*   dst   = (const int*)d_in[6];
    float* out = (float*)d_out;

    (void)in_sizes; (void)n_in; (void)out_size;

    cudaFuncSetAttribute(k_gemm_mma, cudaFuncAttributeMaxDynamicSharedMemorySize, SMEM_BYTES);

    k_init<<<(NODES / 4 + 255) / 256, 256>>>();
    k_deg<<<(NEDGES + 255) / 256, 256>>>(src, dst);
    k_prepB<<<64, 256>>>(W, Wres);
    k_scan1<<<NBLK, 256>>>();
    k_scan2<<<1, 256>>>();
    k_scan3<<<NBLK, 256>>>();
    k_fill<<<(NEDGES + 255) / 256, 256>>>(src, dst);
    k_gather<<<(NODES * 32 + 255) / 256, 256>>>(X);
    k_gemm_mma<<<(NODES + BM - 1) / BM, 512, SMEM_BYTES>>>(X);
    k_finalize<<<1, DD>>>(gamma, beta);
    k_bn<<<(NODES * DD / 4 + 255) / 256, 256>>>(out);
}